// round 4
// baseline (speedup 1.0000x reference)
#include <cuda_runtime.h>
#include <cuda_bf16.h>

// MiscTypeChecker: [B=8192, S=8192] int32 tokens in [0,8), scalar f32 output.
// Backward suffix scan per row with early exit (presence monotone; backward
// first-hit of '1' == last occurrence). Expected read ~4.3MB of 256MB.
//
// Single fused kernel: last-block pattern writes out[0] directly (d_out is
// poisoned, so no pre-zero launch needed). Device-global accumulator is reset
// by the last block each run -> deterministic across graph replays.

#define S_DIM 8192
#define TYPE_RANGE 8

__device__ float    g_partial = 0.0f;
__device__ unsigned g_done    = 0u;

__global__ void __launch_bounds__(256, 1)
mtc_fused_kernel(const int* __restrict__ mpt, float* __restrict__ out,
                 int B, int nblocks, int out_size) {
    __shared__ int bsum;
    if (threadIdx.x == 0) bsum = 0;

    // Defensive: if out has more than 1 element, zero the tail (block 0).
    if (blockIdx.x == 0) {
        for (int i = 1 + (int)threadIdx.x; i < out_size; i += (int)blockDim.x)
            out[i] = 0.0f;
    }
    __syncthreads();

    const int warp = threadIdx.x >> 5;
    const int lane = threadIdx.x & 31;
    const int row  = blockIdx.x * 8 + warp;

    if (row < B) {
        const int* __restrict__ rp = mpt + (long long)row * S_DIM;

        // Head load (rg1/rg2) issued up front so it overlaps the chunk load.
        int h0 = 0, h1 = 1;
        if (lane == 0) {
            const int2 h = *reinterpret_cast<const int2*>(rp);
            h0 = h.x; h1 = h.y;
        }

        unsigned pres = 0u;
        int last1 = -1;

        // Backward chunks of 128 elements: 32 lanes x int4 (coalesced 512B).
        for (int base = S_DIM - 128; base >= 0; base -= 128) {
            const int4 v = reinterpret_cast<const int4*>(rp + base)[lane];
            const int eb = base + lane * 4;

            // presence (reference clips to [0, TYPE_RANGE-1])
            const int cx = min(max(v.x, 0), TYPE_RANGE - 1);
            const int cy = min(max(v.y, 0), TYPE_RANGE - 1);
            const int cz = min(max(v.z, 0), TYPE_RANGE - 1);
            const int cw = min(max(v.w, 0), TYPE_RANGE - 1);
            unsigned p = (1u << cx) | (1u << cy) | (1u << cz) | (1u << cw);

            // highest position of token==1 in this thread's 4 elems
            int l = -1;
            if (v.x == 1) l = eb;
            if (v.y == 1) l = eb + 1;
            if (v.z == 1) l = eb + 2;
            if (v.w == 1) l = eb + 3;

            pres |= __reduce_or_sync(0xffffffffu, p);
            if (last1 < 0) {
                // first hit scanning backward == last occurrence in the row
                last1 = __reduce_max_sync(0xffffffffu, l);
            }
            if (pres == 0xFFu && last1 >= 0) break;  // warp-uniform
        }

        if (lane == 0) {
            int r = ((h0 != 0) + (h1 != 1)) * 4;

            const int miss = TYPE_RANGE - __popc(pres);
            r += miss * miss;

            int rg4 = 6;
            if (last1 > 0 && last1 < S_DIM - 5) {
                // These lines were just fetched by this warp -> L1 hits.
                rg4 = (rp[last1 + 1] != 2) + (rp[last1 + 2] != 4) +
                      (rp[last1 + 3] != 5) + (rp[last1 + 4] != 6) +
                      (rp[last1 + 5] != 3);
            }
            atomicAdd(&bsum, r + rg4);
        }
    }

    __syncthreads();

    if (threadIdx.x == 0) {
        // Float accumulation is exact: integer-valued, total < 2^24.
        atomicAdd(&g_partial, (float)bsum);
        __threadfence();
        const unsigned prev = atomicAdd(&g_done, 1u);
        if (prev == (unsigned)nblocks - 1u) {
            // All blocks' adds are visible (fence + counter ordering).
            const float total = atomicAdd(&g_partial, 0.0f);
            out[0] = total;
            // Reset for the next graph replay (deterministic).
            atomicExch(&g_partial, 0.0f);
            atomicExch(&g_done, 0u);
        }
    }
}

extern "C" void kernel_launch(void* const* d_in, const int* in_sizes, int n_in,
                              void* d_out, int out_size) {
    // Token matrix = largest input (type_range may arrive as a scalar input).
    int big = 0;
    for (int i = 1; i < n_in; i++)
        if (in_sizes[i] > in_sizes[big]) big = i;

    const int* mpt = (const int*)d_in[big];
    float* out = (float*)d_out;
    const int B = in_sizes[big] / S_DIM;
    const int nblocks = (B + 7) / 8;

    mtc_fused_kernel<<<nblocks, 256>>>(mpt, out, B, nblocks, out_size);
}

// round 5
// speedup vs baseline: 1.0996x; 1.0996x over previous
#include <cuda_runtime.h>
#include <cuda_bf16.h>

// MiscTypeChecker: [B=8192, S=8192] int32 tokens in [0,8), scalar f32 output.
// Backward suffix scan per row with early exit (presence monotone; backward
// first-hit of '1' == last occurrence). Expected read ~4.3MB of 256MB.
//
// Single fused kernel, last-block completion via scoped release/acquire
// atomics (NOT __threadfence -> avoids per-block CCTL.IVALL L1 flush on
// Blackwell, which cost ~2.8us in R4).

#define S_DIM 8192
#define TYPE_RANGE 8

__device__ float    g_partial = 0.0f;
__device__ unsigned g_done    = 0u;

__device__ __forceinline__ void red_add_release_f32(float* p, float v) {
    asm volatile("red.release.gpu.global.add.f32 [%0], %1;"
                 :: "l"(p), "f"(v) : "memory");
}
__device__ __forceinline__ unsigned atom_inc_acq_rel(unsigned* p) {
    unsigned old;
    asm volatile("atom.acq_rel.gpu.global.add.u32 %0, [%1], 1;"
                 : "=r"(old) : "l"(p) : "memory");
    return old;
}
__device__ __forceinline__ float ld_acquire_f32(const float* p) {
    float v;
    asm volatile("ld.acquire.gpu.global.f32 %0, [%1];"
                 : "=f"(v) : "l"(p) : "memory");
    return v;
}

__device__ __forceinline__ void chunk_stats(const int* __restrict__ rp,
                                            int base, int lane,
                                            unsigned& p_out, int& l_out) {
    const int4 v = reinterpret_cast<const int4*>(rp + base)[lane];
    const int eb = base + lane * 4;
    // presence (reference clips to [0, TYPE_RANGE-1])
    const int cx = min(max(v.x, 0), TYPE_RANGE - 1);
    const int cy = min(max(v.y, 0), TYPE_RANGE - 1);
    const int cz = min(max(v.z, 0), TYPE_RANGE - 1);
    const int cw = min(max(v.w, 0), TYPE_RANGE - 1);
    p_out = (1u << cx) | (1u << cy) | (1u << cz) | (1u << cw);
    // highest position of token==1 in this thread's 4 elems
    int l = -1;
    if (v.x == 1) l = eb;
    if (v.y == 1) l = eb + 1;
    if (v.z == 1) l = eb + 2;
    if (v.w == 1) l = eb + 3;
    l_out = l;
}

__global__ void __launch_bounds__(256, 1)
mtc_fused_kernel(const int* __restrict__ mpt, float* __restrict__ out,
                 int B, int nblocks, int out_size) {
    __shared__ int bsum;
    if (threadIdx.x == 0) bsum = 0;

    // Defensive: zero any extra output elements (block 0 only; usually none).
    if (blockIdx.x == 0) {
        for (int i = 1 + (int)threadIdx.x; i < out_size; i += (int)blockDim.x)
            out[i] = 0.0f;
    }
    __syncthreads();

    const int warp = threadIdx.x >> 5;
    const int lane = threadIdx.x & 31;
    const int row  = blockIdx.x * 8 + warp;

    if (row < B) {
        const int* __restrict__ rp = mpt + (long long)row * S_DIM;

        // Head load (rg1/rg2) issued up front: overlaps the chunk DRAM trip.
        int h0 = 0, h1 = 1;
        if (lane == 0) {
            const int2 h = *reinterpret_cast<const int2*>(rp);
            h0 = h.x; h1 = h.y;
        }

        // Peeled first chunk (last 128 elems): terminates the scan for
        // essentially every row (P(fallback) ~ 4e-8 for uniform data).
        unsigned p; int l;
        chunk_stats(rp, S_DIM - 128, lane, p, l);
        unsigned pres = __reduce_or_sync(0xffffffffu, p);
        int last1 = __reduce_max_sync(0xffffffffu, l);

        if (!(pres == 0xFFu && last1 >= 0)) {
            for (int base = S_DIM - 256; base >= 0; base -= 128) {
                chunk_stats(rp, base, lane, p, l);
                pres |= __reduce_or_sync(0xffffffffu, p);
                if (last1 < 0)
                    last1 = __reduce_max_sync(0xffffffffu, l);
                if (pres == 0xFFu && last1 >= 0) break;  // warp-uniform
            }
        }

        if (lane == 0) {
            int r = ((h0 != 0) + (h1 != 1)) * 4;

            const int miss = TYPE_RANGE - __popc(pres);
            r += miss * miss;

            int rg4 = 6;
            if (last1 > 0 && last1 < S_DIM - 5) {
                // Lines just fetched by this warp -> L1 hits.
                rg4 = (rp[last1 + 1] != 2) + (rp[last1 + 2] != 4) +
                      (rp[last1 + 3] != 5) + (rp[last1 + 4] != 6) +
                      (rp[last1 + 5] != 3);
            }
            atomicAdd(&bsum, r + rg4);
        }
    }

    __syncthreads();

    if (threadIdx.x == 0) {
        // Float accumulation is exact: integer-valued, total < 2^24.
        red_add_release_f32(&g_partial, (float)bsum);
        const unsigned prev = atom_inc_acq_rel(&g_done);
        if (prev == (unsigned)nblocks - 1u) {
            // acq_rel on the counter + release on the adds => all partials
            // visible to this acquire load.
            out[0] = ld_acquire_f32(&g_partial);
            // Reset for next graph replay (no concurrent writers remain;
            // kernel boundary orders this vs. the next launch).
            g_partial = 0.0f;
            g_done = 0u;
        }
    }
}

extern "C" void kernel_launch(void* const* d_in, const int* in_sizes, int n_in,
                              void* d_out, int out_size) {
    // Token matrix = largest input (type_range may arrive as a scalar input).
    int big = 0;
    for (int i = 1; i < n_in; i++)
        if (in_sizes[i] > in_sizes[big]) big = i;

    const int* mpt = (const int*)d_in[big];
    float* out = (float*)d_out;
    const int B = in_sizes[big] / S_DIM;
    const int nblocks = (B + 7) / 8;

    mtc_fused_kernel<<<nblocks, 256>>>(mpt, out, B, nblocks, out_size);
}